// round 5
// baseline (speedup 1.0000x reference)
#include <cuda_runtime.h>
#include <math.h>

// ---------------- problem constants ----------------
#define NMAX        16384
#define MMAX        4096
#define BINS_TOTAL  65536
#define BIN_OFFSET  24576
#define NORM_F      0.8932438417380023f   // (2/pi)^0.25

// ---------------- device scratch (no allocs allowed) ----------------
static __device__ float  g_wpsi[MMAX];        // trapz weight * psi
static __device__ int    g_pres[BINS_TOTAL];  // presence bitmap
static __device__ int    g_rank[BINS_TOTAL];  // exclusive prefix (rank among sorted unique)
static __device__ float2 g_vals[NMAX];        // pref * factors (complex)
static __device__ int    g_binoff[NMAX];
static __device__ float2 g_binned[NMAX];
static __device__ float2 g_gt[NMAX];
static __device__ float  g_qc[NMAX];
static __device__ float  g_pc[NMAX];
static __device__ float  g_loss;
static __device__ unsigned int g_done;

// ---------------- K0: init / weights / reset accumulators ----------------
__global__ void k_init(const float* __restrict__ x, const float* __restrict__ psi,
                       int M, int N) {
    int i = blockIdx.x * blockDim.x + threadIdx.x;
    if (i == 0) { g_loss = 0.f; g_done = 0u; }
    if (i < BINS_TOTAL) g_pres[i] = 0;
    if (i < N) g_binned[i] = make_float2(0.f, 0.f);
    if (i < M) {
        float w;
        if (M < 2)           w = 0.f;
        else if (i == 0)     w = 0.5f * (x[1] - x[0]);
        else if (i == M - 1) w = 0.5f * (x[M-1] - x[M-2]);
        else                 w = 0.5f * (x[i+1] - x[i-1]);
        g_wpsi[i] = w * psi[i];
    }
}

// ---------------- K1: per-trajectory binning + prefactor ----------------
__global__ void k_prep(const float* __restrict__ fre, const float* __restrict__ fim,
                       const float* __restrict__ qre, const float* __restrict__ qim,
                       const float* __restrict__ pre, const float* __restrict__ pim,
                       int N) {
    int j = blockIdx.x * blockDim.x + threadIdx.x;
    if (j >= N) return;

    float qf = qre[j] - 0.5f * pim[j];           // Re(xi)/(2g)
    float pf = 2.0f * qim[j] + pre[j];           // Im(xi)

    // dq = 0.125 (exact), dp = 0.15625 (exact). IEEE divides so floor matches
    // jnp bit-exactly at bin boundaries (a flipped bin moves an O(100) value).
    float qb = floorf(__fdiv_rn(qf - (-8.0f),  0.125f));
    float pb = floorf(__fdiv_rn(pf - (-10.0f), 0.15625f));

    int bin = (int)(qb * 128.0f + pb);           // trunc like astype(int32)
    int off = bin + BIN_OFFSET;
    off = min(max(off, 0), BINS_TOTAL - 1);
    g_pres[off]  = 1;
    g_binoff[j]  = off;

    g_qc[j] = (qb + 0.5f) * 0.125f   + (-8.0f);
    g_pc[j] = (pb + 0.5f) * 0.15625f + (-10.0f);

    float qi  = qim[j];
    float prf = NORM_F * expf(qi * qi);
    float s, c;
    sincosf(pre[j] * qi, &s, &c);                // accurate: only 16K calls
    float prRe = fminf(fmaxf(prf * c, -100.0f), 100.0f);
    float prIm = fminf(fmaxf(prf * s, -100.0f), 100.0f);

    float fr = fre[j], fi = fim[j];
    g_vals[j] = make_float2(prRe * fr - prIm * fi,
                            prRe * fi + prIm * fr);
}

// ---------------- K2: exclusive scan of presence bitmap (single block) ----------------
__global__ void k_scan() {
    const int t = threadIdx.x;          // 1024 threads, 64 entries each
    const int base = t * 64;
    int sum = 0;
    #pragma unroll 8
    for (int k = 0; k < 64; k++) sum += g_pres[base + k];

    __shared__ int sh[1024];
    sh[t] = sum;
    __syncthreads();
    for (int off = 1; off < 1024; off <<= 1) {
        int v = (t >= off) ? sh[t - off] : 0;
        __syncthreads();
        if (t >= off) sh[t] += v;
        __syncthreads();
    }
    int running = (t > 0) ? sh[t - 1] : 0;      // exclusive prefix of this chunk
    for (int k = 0; k < 64; k++) {
        g_rank[base + k] = running;
        running += g_pres[base + k];
    }
}

// ---------------- K3: scatter-add vals into compacted bins ----------------
__global__ void k_scatter(int N) {
    int j = blockIdx.x * blockDim.x + threadIdx.x;
    if (j >= N) return;
    int ind = g_rank[g_binoff[j]];
    float2 v = g_vals[j];
    atomicAdd(&g_binned[ind].x, v.x);
    atomicAdd(&g_binned[ind].y, v.y);
}

// ---------------- K4: gt[j] = trapz( conj(gf_j) * psi ) ----------------
// one warp per trajectory, 4 trajectories per block; x and w*psi staged in smem.
__global__ void __launch_bounds__(128) k_gt(const float* __restrict__ x, int M, int N) {
    __shared__ float sx[MMAX];
    __shared__ float sw[MMAX];
    const int tid = threadIdx.x;
    for (int i = tid; i < M; i += 128) { sx[i] = x[i]; sw[i] = g_wpsi[i]; }
    __syncthreads();

    const int warp = tid >> 5, lane = tid & 31;
    const int j = blockIdx.x * 4 + warp;
    if (j >= N || M < 2) return;

    const float qc = g_qc[j], pc = g_pc[j];
    const float x0 = sx[0];
    const float h  = sx[1] - sx[0];

    // Gaussian support truncation: exp(-64) * w ~ 1e-30, far below fp32 noise.
    int lo = (int)((qc - 8.0f - x0) / h);       lo = max(lo, 0);
    int hi = (int)((qc + 8.0f - x0) / h) + 2;   hi = min(hi, M);

    float ar = 0.f, ai = 0.f;
    for (int m = lo + lane; m < hi; m += 32) {
        float dx = sx[m] - qc;
        float e  = __expf(-dx * dx) * sw[m];
        float s, c;
        __sincosf(pc * dx, &s, &c);             // error damped by Gaussian at large arg
        ar = fmaf(e,  c, ar);
        ai = fmaf(-e, s, ai);                   // conj: cos - i sin
    }
    #pragma unroll
    for (int o = 16; o; o >>= 1) {
        ar += __shfl_down_sync(0xffffffffu, ar, o);
        ai += __shfl_down_sync(0xffffffffu, ai, o);
    }
    if (lane == 0) g_gt[j] = make_float2(NORM_F * ar, NORM_F * ai);
}

// ---------------- K5: |binned - gt|^2 -> global atomic; last block writes sqrt ----------------
__global__ void k_loss(float* __restrict__ out, int N, int nblocks) {
    __shared__ float sh[256];
    __shared__ bool  last;
    int j = blockIdx.x * 256 + threadIdx.x;
    float t = 0.f;
    if (j < N) {
        float2 b = g_binned[j], g = g_gt[j];
        float dr = b.x - g.x, di = b.y - g.y;
        t = dr * dr + di * di;
    }
    sh[threadIdx.x] = t;
    __syncthreads();
    for (int o = 128; o; o >>= 1) {
        if (threadIdx.x < o) sh[threadIdx.x] += sh[threadIdx.x + o];
        __syncthreads();
    }
    if (threadIdx.x == 0) {
        atomicAdd(&g_loss, sh[0]);
        __threadfence();
        // atomicInc wraps to 0 after nblocks increments -> deterministic across
        // graph replays without an extra reset.
        unsigned int prev = atomicInc(&g_done, (unsigned int)(nblocks - 1));
        last = (prev == (unsigned int)(nblocks - 1));
    }
    __syncthreads();
    if (last && threadIdx.x == 0) {
        // L2-coherent read (plain LDG could hit a stale L1 line).
        float total = atomicAdd(&g_loss, 0.0f);
        out[0] = sqrtf(total);
    }
}

// ---------------- launch ----------------
extern "C" void kernel_launch(void* const* d_in, const int* in_sizes, int n_in,
                              void* d_out, int out_size) {
    const float* fre = (const float*)d_in[0];
    const float* fim = (const float*)d_in[1];
    const float* qre = (const float*)d_in[2];
    const float* qim = (const float*)d_in[3];
    const float* pre = (const float*)d_in[4];
    const float* pim = (const float*)d_in[5];
    const float* x   = (const float*)d_in[6];
    const float* psi = (const float*)d_in[7];

    int N = in_sizes[0];
    int M = in_sizes[6];
    if (N > NMAX) N = NMAX;
    if (M > MMAX) M = MMAX;

    int nb = (N + 255) / 256;
    k_init   <<<(BINS_TOTAL + 255) / 256, 256>>>(x, psi, M, N);
    k_prep   <<<(N + 255) / 256, 256>>>(fre, fim, qre, qim, pre, pim, N);
    k_scan   <<<1, 1024>>>();
    k_scatter<<<(N + 255) / 256, 256>>>(N);
    k_gt     <<<(N + 3) / 4, 128>>>(x, M, N);
    k_loss   <<<nb, 256>>>((float*)d_out, N, nb);
}

// round 7
// speedup vs baseline: 2.7586x; 2.7586x over previous
#include <cuda_runtime.h>
#include <math.h>

// ---------------- problem constants ----------------
#define NMAX        16384
#define MMAX        4096
#define BINS_TOTAL  65536
#define BIN_OFFSET  24576
#define NORM_F      0.8932438417380023f   // (2/pi)^0.25

// ---------------- device scratch (statically zero-initialized; each kernel
// resets what it consumed so graph replays see a clean state) ----------------
static __device__ float  g_wpsi[MMAX];        // trapz weight * psi
static __device__ int    g_pres[BINS_TOTAL];  // presence (0/1); zeroed by k_scan pass 2
static __device__ int    g_rank[BINS_TOTAL];  // rank among sorted unique bins
static __device__ float2 g_vals[NMAX];        // pref * factors (complex)
static __device__ int    g_binoff[NMAX];
static __device__ float2 g_binned[NMAX];      // zeroed by k_scan each call
static __device__ float  g_qc[NMAX];
static __device__ float  g_pc[NMAX];
static __device__ float  g_loss;              // reset by last k_gt_loss block
static __device__ unsigned int g_done;        // atomicInc wraps -> self-resetting

// ---------------- K1: binning + prefactor + trapz weights ----------------
__global__ void k_prep(const float* __restrict__ fre, const float* __restrict__ fim,
                       const float* __restrict__ qre, const float* __restrict__ qim,
                       const float* __restrict__ pre, const float* __restrict__ pim,
                       const float* __restrict__ x,   const float* __restrict__ psi,
                       int N, int M) {
    int j = blockIdx.x * blockDim.x + threadIdx.x;
    if (j < M) {                              // fold trapz-weight*psi computation in
        float w;
        if (M < 2)           w = 0.f;
        else if (j == 0)     w = 0.5f * (x[1] - x[0]);
        else if (j == M - 1) w = 0.5f * (x[M-1] - x[M-2]);
        else                 w = 0.5f * (x[j+1] - x[j-1]);
        g_wpsi[j] = w * psi[j];
    }
    if (j >= N) return;

    float qf = qre[j] - 0.5f * pim[j];           // Re(xi)/(2g)
    float pf = 2.0f * qim[j] + pre[j];           // Im(xi)

    // dq = 0.125 (exact), dp = 0.15625 (exact). IEEE divides so floor matches
    // jnp bit-exactly at bin boundaries (a flipped bin moves an O(100) value).
    float qb = floorf(__fdiv_rn(qf - (-8.0f),  0.125f));
    float pb = floorf(__fdiv_rn(pf - (-10.0f), 0.15625f));

    int bin = (int)(qb * 128.0f + pb);           // trunc like astype(int32)
    int off = bin + BIN_OFFSET;
    off = min(max(off, 0), BINS_TOTAL - 1);
    g_pres[off]  = 1;
    g_binoff[j]  = off;

    g_qc[j] = (qb + 0.5f) * 0.125f   + (-8.0f);
    g_pc[j] = (pb + 0.5f) * 0.15625f + (-10.0f);

    float qi  = qim[j];
    float prf = NORM_F * expf(qi * qi);
    float s, c;
    sincosf(pre[j] * qi, &s, &c);                // accurate: only 16K calls
    float prRe = fminf(fmaxf(prf * c, -100.0f), 100.0f);
    float prIm = fminf(fmaxf(prf * s, -100.0f), 100.0f);

    float fr = fre[j], fi = fim[j];
    g_vals[j] = make_float2(prRe * fr - prIm * fi,
                            prRe * fi + prIm * fr);
}

// ---------------- K2: ballot-based exclusive scan, coalesced, self-cleaning ----
// 1024 threads = 32 warps; warp w owns entries [w*2048, (w+1)*2048).
// Also zeroes g_binned for the scatter kernel.
__global__ void __launch_bounds__(1024) k_scan(int N) {
    const int tid  = threadIdx.x;
    const int warp = tid >> 5, lane = tid & 31;
    const unsigned FULL = 0xffffffffu;
    const unsigned ltmask = (1u << lane) - 1u;
    const int base = warp * 2048;

    __shared__ int wtot[32], woff[32];

    // pass 1: per-warp presence count (coalesced: lanes stride 1, k strides 32)
    int cnt = 0;
    #pragma unroll 4
    for (int k = 0; k < 64; k++) {
        int p = g_pres[base + k * 32 + lane];
        unsigned mask = __ballot_sync(FULL, p != 0);
        cnt += __popc(mask);                 // same value in all lanes
    }
    if (lane == 0) wtot[warp] = cnt;
    __syncthreads();

    // exclusive scan of 32 warp totals (warp 0)
    if (warp == 0) {
        int v = wtot[lane];
        int inc = v;
        #pragma unroll
        for (int o = 1; o < 32; o <<= 1) {
            int n = __shfl_up_sync(FULL, inc, o);
            if (lane >= o) inc += n;
        }
        woff[lane] = inc - v;
    }
    __syncthreads();

    // pass 2: write ranks, reset presence
    int running = woff[warp];
    #pragma unroll 4
    for (int k = 0; k < 64; k++) {
        int idx = base + k * 32 + lane;
        int p = g_pres[idx];
        unsigned mask = __ballot_sync(FULL, p != 0);
        g_rank[idx] = running + __popc(mask & ltmask);
        g_pres[idx] = 0;                     // self-clean for next call
        running += __popc(mask);
    }

    // zero g_binned (16384 float2, coalesced)
    for (int i = tid; i < N; i += 1024)
        g_binned[i] = make_float2(0.f, 0.f);
}

// ---------------- K3: scatter-add vals into compacted bins ----------------
__global__ void k_scatter(int N) {
    int j = blockIdx.x * blockDim.x + threadIdx.x;
    if (j >= N) return;
    int ind = g_rank[g_binoff[j]];
    float2 v = g_vals[j];
    atomicAdd(&g_binned[ind].x, v.x);
    atomicAdd(&g_binned[ind].y, v.y);
}

// ---------------- K4: gt = trapz(conj(gf)*psi), fused with loss reduction ----
// one warp per trajectory, 4 trajectories per block; x and w*psi staged in smem.
__global__ void __launch_bounds__(128) k_gt_loss(const float* __restrict__ x,
                                                 float* __restrict__ out,
                                                 int M, int N, int nblocks) {
    __shared__ float sx[MMAX];
    __shared__ float sw[MMAX];
    __shared__ float sred[4];
    const int tid = threadIdx.x;
    for (int i = tid; i < M; i += 128) { sx[i] = x[i]; sw[i] = g_wpsi[i]; }
    __syncthreads();

    const int warp = tid >> 5, lane = tid & 31;
    const int j = blockIdx.x * 4 + warp;

    float contrib = 0.f;
    if (j < N && M >= 2) {
        const float qc = g_qc[j], pc = g_pc[j];
        const float x0 = sx[0];
        const float h  = sx[1] - sx[0];

        // Gaussian support truncation: exp(-64)*w ~ 1e-30, below fp32 noise.
        int lo = (int)((qc - 8.0f - x0) / h);       lo = max(lo, 0);
        int hi = (int)((qc + 8.0f - x0) / h) + 2;   hi = min(hi, M);

        float ar = 0.f, ai = 0.f;
        for (int m = lo + lane; m < hi; m += 32) {
            float dx = sx[m] - qc;
            float e  = __expf(-dx * dx) * sw[m];
            float s, c;
            __sincosf(pc * dx, &s, &c);         // error damped by Gaussian
            ar = fmaf(e,  c, ar);
            ai = fmaf(-e, s, ai);               // conj: cos - i sin
        }
        #pragma unroll
        for (int o = 16; o; o >>= 1) {
            ar += __shfl_down_sync(0xffffffffu, ar, o);
            ai += __shfl_down_sync(0xffffffffu, ai, o);
        }
        if (lane == 0) {
            float gtr = NORM_F * ar, gti = NORM_F * ai;
            float2 b = g_binned[j];             // L1 fresh: flushed per launch
            float dr = b.x - gtr, di = b.y - gti;
            contrib = dr * dr + di * di;
        }
    }
    if (lane == 0) sred[warp] = contrib;
    __syncthreads();

    if (tid == 0) {
        float t = sred[0] + sred[1] + sred[2] + sred[3];
        atomicAdd(&g_loss, t);
        __threadfence();
        // wraps to 0 after nblocks increments -> deterministic across replays
        unsigned int prev = atomicInc(&g_done, (unsigned int)(nblocks - 1));
        if (prev == (unsigned int)(nblocks - 1)) {
            float total = atomicAdd(&g_loss, 0.0f);   // L2-coherent read
            out[0] = sqrtf(total);
            atomicExch(&g_loss, 0.0f);                // reset for next replay
        }
    }
}

// ---------------- launch (4 kernels) ----------------
extern "C" void kernel_launch(void* const* d_in, const int* in_sizes, int n_in,
                              void* d_out, int out_size) {
    const float* fre = (const float*)d_in[0];
    const float* fim = (const float*)d_in[1];
    const float* qre = (const float*)d_in[2];
    const float* qim = (const float*)d_in[3];
    const float* pre = (const float*)d_in[4];
    const float* pim = (const float*)d_in[5];
    const float* x   = (const float*)d_in[6];
    const float* psi = (const float*)d_in[7];

    int N = in_sizes[0];
    int M = in_sizes[6];
    if (N > NMAX) N = NMAX;
    if (M > MMAX) M = MMAX;

    int nb = (N + 3) / 4;
    k_prep   <<<(N + 255) / 256, 256>>>(fre, fim, qre, qim, pre, pim, x, psi, N, M);
    k_scan   <<<1, 1024>>>(N);
    k_scatter<<<(N + 255) / 256, 256>>>(N);
    k_gt_loss<<<nb, 128>>>(x, (float*)d_out, M, N, nb);
}